// round 1
// baseline (speedup 1.0000x reference)
#include <cuda_runtime.h>
#include <math.h>

#define D 128
#define NMAX 20000
#define ROWS 16
#define LN_EPS 1e-5f

// ---------------- device scratch (no allocs allowed) ----------------
__device__ unsigned g_agg[NMAX * D];   // orderable-uint encoded running max
__device__ float    g_h[NMAX * D];     // h after first LayerNorm
__device__ int      g_i64;             // 1 if edge_index buffer is int64

// monotonic float<->orderable-uint mapping (total order matches float order)
__device__ __forceinline__ unsigned encf(float f) {
    unsigned u = __float_as_uint(f);
    return (u & 0x80000000u) ? ~u : (u | 0x80000000u);
}
__device__ __forceinline__ float decf(unsigned u) {
    return (u & 0x80000000u) ? __uint_as_float(u ^ 0x80000000u)
                             : __uint_as_float(~u);
}
__device__ __forceinline__ float gelu_exact(float v) { return v * normcdff(v); }

// ---------------- K0: detect int64 vs int32 edge_index ----------------
// int64 little-endian: every odd 32-bit word is the (zero) high half.
// int32: odd words are random node ids in [0,20000) -> essentially never all zero.
__global__ void k_detect(const int* __restrict__ ei) {
    __shared__ int bad;
    if (threadIdx.x == 0) bad = 0;
    __syncthreads();
    int any = 0;
    for (int i = threadIdx.x; i < 1024; i += blockDim.x)
        if (ei[2 * i + 1] != 0) any = 1;
    if (any) atomicOr(&bad, 1);
    __syncthreads();
    if (threadIdx.x == 0) g_i64 = (bad == 0) ? 1 : 0;
}

// ---------------- K1: init agg sentinel ----------------
__global__ void k_init(int total) {
    int i = blockIdx.x * blockDim.x + threadIdx.x;
    if (i < total) g_agg[i] = 0u;   // sentinel: "empty segment"
}

// ---------------- K2: scatter-max  msg = x[src]*w  ->  agg[dst] ----------------
// 32 threads per edge, float4 per thread. Read-filtered atomics (monotone-safe).
__global__ void k_scatter(const int* __restrict__ ei, const float* __restrict__ ew,
                          const float* __restrict__ x, int e) {
    long long idx = (long long)blockIdx.x * blockDim.x + threadIdx.x;
    long long total = (long long)e * 32;
    if (idx >= total) return;
    int edge = (int)(idx >> 5);
    int l = (int)(idx & 31);
    int src, dst;
    if (g_i64) { src = ei[2 * edge]; dst = ei[2 * (e + edge)]; }
    else       { src = ei[edge];     dst = ei[e + edge]; }
    float w = ew[edge];
    float4 xv = ((const float4*)x)[src * 32 + l];
    unsigned e0 = encf(xv.x * w), e1 = encf(xv.y * w);
    unsigned e2 = encf(xv.z * w), e3 = encf(xv.w * w);
    unsigned* p = g_agg + dst * D + l * 4;
    uint4 cur = __ldcg((const uint4*)p);
    if (e0 > cur.x) atomicMax(p + 0, e0);
    if (e1 > cur.y) atomicMax(p + 1, e1);
    if (e2 > cur.z) atomicMax(p + 2, e2);
    if (e3 > cur.w) atomicMax(p + 3, e3);
}

// ---------------- K3: h = LN( gelu(agg@Wrel^T + b + x@Wroot^T) + x ) ----------------
// Persistent grid; both 128x128 weights cached in smem (132-float padded rows
// -> conflict-free LDS.128). 512 threads = 4 row-slots x 128 cols; each thread
// accumulates 4 rows x 1 column in registers.
__global__ void k_gemm1(const float* __restrict__ x, const float* __restrict__ Wrel,
                        const float* __restrict__ brel, const float* __restrict__ Wroot,
                        const float* __restrict__ gamma, const float* __restrict__ beta,
                        int n) {
    extern __shared__ float sm[];
    float* wrel  = sm;                 // 128*132
    float* wroot = wrel + D * 132;     // 128*132
    float* arel  = wroot + D * 132;    // ROWS*128
    float* aroot = arel + ROWS * D;    // ROWS*128  (x rows, also skip source)
    float* sred  = aroot + ROWS * D;   // ROWS*4
    float* qred  = sred + ROWS * 4;    // ROWS*4

    int tid  = threadIdx.x;
    int t    = tid & (D - 1);
    int slot = tid >> 7;          // 0..3
    int wwid = (tid >> 5) & 3;    // warp within slot
    int lane = tid & 31;

    for (int i = tid; i < D * D; i += blockDim.x) {
        int r = i >> 7, c = i & 127;
        wrel[r * 132 + c]  = Wrel[i];
        wroot[r * 132 + c] = Wroot[i];
    }
    float bt = brel[t], gt = gamma[t], be = beta[t];
    __syncthreads();

    int nchunks = (n + ROWS - 1) / ROWS;
    for (int ch = blockIdx.x; ch < nchunks; ch += gridDim.x) {
        int row0 = ch * ROWS;
        for (int i = tid; i < ROWS * D; i += blockDim.x) {
            int r = row0 + (i >> 7);
            float av = 0.f, xv = 0.f;
            if (r < n) {
                unsigned u = g_agg[r * D + (i & 127)];
                av = (u == 0u) ? 0.f : decf(u);   // empty segment -> 0 (PyG fill)
                xv = x[r * D + (i & 127)];
            }
            arel[i] = av; aroot[i] = xv;
        }
        __syncthreads();

        float acc[4] = {0.f, 0.f, 0.f, 0.f};
        const float4* w14 = (const float4*)(wrel + t * 132);
        const float4* w24 = (const float4*)(wroot + t * 132);
        #pragma unroll 4
        for (int k4 = 0; k4 < 32; k4++) {
            float4 w1 = w14[k4], w2 = w24[k4];
            #pragma unroll
            for (int j = 0; j < 4; j++) {
                float4 a1 = *(const float4*)(arel  + (slot * 4 + j) * D + k4 * 4);
                float4 a2 = *(const float4*)(aroot + (slot * 4 + j) * D + k4 * 4);
                acc[j] = fmaf(a1.x, w1.x, acc[j]); acc[j] = fmaf(a1.y, w1.y, acc[j]);
                acc[j] = fmaf(a1.z, w1.z, acc[j]); acc[j] = fmaf(a1.w, w1.w, acc[j]);
                acc[j] = fmaf(a2.x, w2.x, acc[j]); acc[j] = fmaf(a2.y, w2.y, acc[j]);
                acc[j] = fmaf(a2.z, w2.z, acc[j]); acc[j] = fmaf(a2.w, w2.w, acc[j]);
            }
        }

        float hv[4];
        #pragma unroll
        for (int j = 0; j < 4; j++) {
            int rl = slot * 4 + j;
            float hpre = acc[j] + bt;
            hv[j] = gelu_exact(hpre) + aroot[rl * D + t];
            float s = hv[j], q = hv[j] * hv[j];
            #pragma unroll
            for (int o = 16; o; o >>= 1) {
                s += __shfl_xor_sync(0xffffffffu, s, o);
                q += __shfl_xor_sync(0xffffffffu, q, o);
            }
            if (lane == 0) { sred[rl * 4 + wwid] = s; qred[rl * 4 + wwid] = q; }
        }
        __syncthreads();
        #pragma unroll
        for (int j = 0; j < 4; j++) {
            int rl = slot * 4 + j;
            int r = row0 + rl;
            float s = sred[rl * 4 + 0] + sred[rl * 4 + 1] + sred[rl * 4 + 2] + sred[rl * 4 + 3];
            float q = qred[rl * 4 + 0] + qred[rl * 4 + 1] + qred[rl * 4 + 2] + qred[rl * 4 + 3];
            float mu  = s * (1.f / D);
            float var = fmaxf(q * (1.f / D) - mu * mu, 0.f);
            float y = (hv[j] - mu) * rsqrtf(var + LN_EPS) * gt + be;
            if (r < n) g_h[r * D + t] = y;
        }
        __syncthreads();
    }
}

// ---------------- K4: out = LN( gelu(h@linW^T + lb) + h ) ----------------
__global__ void k_gemm2(const float* __restrict__ lw, const float* __restrict__ lb,
                        const float* __restrict__ gamma, const float* __restrict__ beta,
                        float* __restrict__ out, int n) {
    extern __shared__ float sm[];
    float* ws   = sm;               // 128*132
    float* as   = ws + D * 132;     // ROWS*128 (h rows; also skip source)
    float* sred = as + ROWS * D;
    float* qred = sred + ROWS * 4;

    int tid  = threadIdx.x;
    int t    = tid & (D - 1);
    int slot = tid >> 7;
    int wwid = (tid >> 5) & 3;
    int lane = tid & 31;

    for (int i = tid; i < D * D; i += blockDim.x) {
        int r = i >> 7, c = i & 127;
        ws[r * 132 + c] = lw[i];
    }
    float bt = lb[t], gt = gamma[t], be = beta[t];
    __syncthreads();

    int nchunks = (n + ROWS - 1) / ROWS;
    for (int ch = blockIdx.x; ch < nchunks; ch += gridDim.x) {
        int row0 = ch * ROWS;
        for (int i = tid; i < ROWS * D; i += blockDim.x) {
            int r = row0 + (i >> 7);
            as[i] = (r < n) ? g_h[r * D + (i & 127)] : 0.f;
        }
        __syncthreads();

        float acc[4] = {0.f, 0.f, 0.f, 0.f};
        const float4* w4 = (const float4*)(ws + t * 132);
        #pragma unroll 4
        for (int k4 = 0; k4 < 32; k4++) {
            float4 w1 = w4[k4];
            #pragma unroll
            for (int j = 0; j < 4; j++) {
                float4 a1 = *(const float4*)(as + (slot * 4 + j) * D + k4 * 4);
                acc[j] = fmaf(a1.x, w1.x, acc[j]); acc[j] = fmaf(a1.y, w1.y, acc[j]);
                acc[j] = fmaf(a1.z, w1.z, acc[j]); acc[j] = fmaf(a1.w, w1.w, acc[j]);
            }
        }

        float hv[4];
        #pragma unroll
        for (int j = 0; j < 4; j++) {
            int rl = slot * 4 + j;
            float hpre = acc[j] + bt;
            hv[j] = gelu_exact(hpre) + as[rl * D + t];
            float s = hv[j], q = hv[j] * hv[j];
            #pragma unroll
            for (int o = 16; o; o >>= 1) {
                s += __shfl_xor_sync(0xffffffffu, s, o);
                q += __shfl_xor_sync(0xffffffffu, q, o);
            }
            if (lane == 0) { sred[rl * 4 + wwid] = s; qred[rl * 4 + wwid] = q; }
        }
        __syncthreads();
        #pragma unroll
        for (int j = 0; j < 4; j++) {
            int rl = slot * 4 + j;
            int r = row0 + rl;
            float s = sred[rl * 4 + 0] + sred[rl * 4 + 1] + sred[rl * 4 + 2] + sred[rl * 4 + 3];
            float q = qred[rl * 4 + 0] + qred[rl * 4 + 1] + qred[rl * 4 + 2] + qred[rl * 4 + 3];
            float mu  = s * (1.f / D);
            float var = fmaxf(q * (1.f / D) - mu * mu, 0.f);
            float y = (hv[j] - mu) * rsqrtf(var + LN_EPS) * gt + be;
            if (r < n) out[r * D + t] = y;
        }
        __syncthreads();
    }
}

// ---------------- launch ----------------
extern "C" void kernel_launch(void* const* d_in, const int* in_sizes, int n_in,
                              void* d_out, int out_size) {
    const float* x     = (const float*)d_in[0];
    const int*   ei    = (const int*)d_in[1];   // int32 view; int64 handled via g_i64
    const float* ew    = (const float*)d_in[2];
    const float* Wrel  = (const float*)d_in[3];
    const float* brel  = (const float*)d_in[4];
    const float* Wroot = (const float*)d_in[5];
    const float* linW  = (const float*)d_in[6];
    const float* linb  = (const float*)d_in[7];
    const float* gamma = (const float*)d_in[8];
    const float* beta  = (const float*)d_in[9];
    float* out = (float*)d_out;

    int n = in_sizes[0] / D;
    int e = in_sizes[2];

    size_t smem1 = (size_t)(2 * D * 132 + 2 * ROWS * D + 2 * ROWS * 4) * 4;  // 152,064 B
    size_t smem2 = (size_t)(D * 132 + ROWS * D + 2 * ROWS * 4) * 4;          //  76,288 B
    cudaFuncSetAttribute(k_gemm1, cudaFuncAttributeMaxDynamicSharedMemorySize, (int)smem1);
    cudaFuncSetAttribute(k_gemm2, cudaFuncAttributeMaxDynamicSharedMemorySize, (int)smem2);

    k_detect<<<1, 256>>>(ei);
    k_init<<<(n * D + 255) / 256, 256>>>(n * D);
    long long items = (long long)e * 32;
    int sblocks = (int)((items + 255) / 256);
    k_scatter<<<sblocks, 256>>>(ei, ew, x, e);
    k_gemm1<<<148, 512, smem1>>>(x, Wrel, brel, Wroot, gamma, beta, n);
    k_gemm2<<<148, 512, smem2>>>(linW, linb, gamma, beta, out, n);
    if (out_size >= n * D + e)
        cudaMemcpyAsync(out + (size_t)n * D, ew, (size_t)e * sizeof(float),
                        cudaMemcpyDeviceToDevice);
}

// round 2
// speedup vs baseline: 2.2047x; 2.2047x over previous
#include <cuda_runtime.h>
#include <math.h>

#define D 128
#define NMAX 20000
#define EMAX 640000
#define LN_EPS 1e-5f

// ---------------- device scratch (no allocs allowed) ----------------
__device__ float g_aggf[NMAX * D];     // segment-max result (0 for empty)
__device__ float g_h[NMAX * D];        // h after first LayerNorm
__device__ int   g_cnt[NMAX];          // per-node degree counters
__device__ int   g_off[NMAX + 1];      // CSR offsets
__device__ int   g_pos[EMAX];          // per-edge slot within its dst bucket
__device__ int   g_src[EMAX];          // CSR-ordered source ids
__device__ float g_w[EMAX];            // CSR-ordered edge weights
__device__ int   g_i64;                // 1 if edge_index buffer is int64

__device__ __forceinline__ float gelu_exact(float v) { return v * normcdff(v); }

__device__ __forceinline__ void fma4(float4& acc, float a, const float4& w) {
    acc.x = fmaf(a, w.x, acc.x); acc.y = fmaf(a, w.y, acc.y);
    acc.z = fmaf(a, w.z, acc.z); acc.w = fmaf(a, w.w, acc.w);
}

// ---------------- K0: detect int64 vs int32 edge_index ----------------
__global__ void k_detect(const int* __restrict__ ei) {
    __shared__ int bad;
    if (threadIdx.x == 0) bad = 0;
    __syncthreads();
    int any = 0;
    for (int i = threadIdx.x; i < 1024; i += blockDim.x)
        if (ei[2 * i + 1] != 0) any = 1;
    if (any) atomicOr(&bad, 1);
    __syncthreads();
    if (threadIdx.x == 0) g_i64 = (bad == 0) ? 1 : 0;
}

// ---------------- CSR build ----------------
__global__ void k_zero(int n) {
    int i = blockIdx.x * blockDim.x + threadIdx.x;
    if (i < n) g_cnt[i] = 0;
}

__global__ void k_count(const int* __restrict__ ei, int e) {
    int i = blockIdx.x * blockDim.x + threadIdx.x;
    if (i >= e) return;
    int dst = g_i64 ? ei[2 * (e + i)] : ei[e + i];
    g_pos[i] = atomicAdd(&g_cnt[dst], 1);
}

// single-block exclusive scan over g_cnt[0..n) -> g_off
__global__ void k_scan(int n) {
    __shared__ int wsum[32];
    __shared__ int carry;
    int tid = threadIdx.x, lane = tid & 31, wid = tid >> 5;
    if (tid == 0) carry = 0;
    __syncthreads();
    for (int base = 0; base < n; base += 1024) {
        int i = base + tid;
        int v = (i < n) ? g_cnt[i] : 0;
        int s = v;
        #pragma unroll
        for (int o = 1; o < 32; o <<= 1) {
            int t = __shfl_up_sync(0xffffffffu, s, o);
            if (lane >= o) s += t;
        }
        if (lane == 31) wsum[wid] = s;
        __syncthreads();
        if (wid == 0) {
            int ws = wsum[lane];
            #pragma unroll
            for (int o = 1; o < 32; o <<= 1) {
                int t = __shfl_up_sync(0xffffffffu, ws, o);
                if (lane >= o) ws += t;
            }
            wsum[lane] = ws;
        }
        __syncthreads();
        int excl = carry + s - v + (wid > 0 ? wsum[wid - 1] : 0);
        if (i < n) g_off[i] = excl;
        __syncthreads();
        if (tid == 0) carry += wsum[31];
        __syncthreads();
    }
    if (threadIdx.x == 0) g_off[n] = carry;
}

__global__ void k_place(const int* __restrict__ ei, const float* __restrict__ ew, int e) {
    int i = blockIdx.x * blockDim.x + threadIdx.x;
    if (i >= e) return;
    int src, dst;
    if (g_i64) { src = ei[2 * i]; dst = ei[2 * (e + i)]; }
    else       { src = ei[i];     dst = ei[e + i]; }
    int idx = g_off[dst] + g_pos[i];
    g_src[idx] = src;
    g_w[idx]   = ew[i];
}

// ---------------- per-node gather-max: one warp per node ----------------
__global__ void k_agg(const float* __restrict__ x, int n) {
    int wp = threadIdx.x >> 5, lane = threadIdx.x & 31;
    int node = blockIdx.x * 8 + wp;
    if (node >= n) return;
    int s0 = g_off[node], s1 = g_off[node + 1];
    const float4* x4 = (const float4*)x;
    float4 m = make_float4(-INFINITY, -INFINITY, -INFINITY, -INFINITY);
    int i = s0;
    for (; i + 1 < s1; i += 2) {
        int sa = g_src[i], sb = g_src[i + 1];
        float wa = g_w[i], wb = g_w[i + 1];
        float4 va = x4[sa * 32 + lane];
        float4 vb = x4[sb * 32 + lane];
        m.x = fmaxf(m.x, va.x * wa); m.y = fmaxf(m.y, va.y * wa);
        m.z = fmaxf(m.z, va.z * wa); m.w = fmaxf(m.w, va.w * wa);
        m.x = fmaxf(m.x, vb.x * wb); m.y = fmaxf(m.y, vb.y * wb);
        m.z = fmaxf(m.z, vb.z * wb); m.w = fmaxf(m.w, vb.w * wb);
    }
    if (i < s1) {
        int sa = g_src[i]; float wa = g_w[i];
        float4 va = x4[sa * 32 + lane];
        m.x = fmaxf(m.x, va.x * wa); m.y = fmaxf(m.y, va.y * wa);
        m.z = fmaxf(m.z, va.z * wa); m.w = fmaxf(m.w, va.w * wa);
    }
    if (s1 <= s0) m = make_float4(0.f, 0.f, 0.f, 0.f);
    ((float4*)g_aggf)[node * 32 + lane] = m;
}

// ---------------- K3: h = LN( gelu(agg@Wrel^T + b + x@Wroot^T) + x ) ----------------
// 256 threads; chunk = 32 rows x 128 cols; thread tile 4 rows x 4 cols.
// Weights staged TRANSPOSED (wt[k][c], pitch 132): conflict-free float4 reads.
// A tiles row-major pitch 132: broadcast float4 reads, conflict-free staging.
__global__ void __launch_bounds__(256, 1)
k_gemm1(const float* __restrict__ x, const float* __restrict__ Wrel,
        const float* __restrict__ brel, const float* __restrict__ Wroot,
        const float* __restrict__ gamma, const float* __restrict__ beta, int n) {
    extern __shared__ float sm[];
    float* wtr = sm;                    // [128][132] transposed W_rel
    float* wto = wtr + 128 * 132;       // [128][132] transposed W_root
    float* asr = wto + 128 * 132;       // [32][132]  agg rows
    float* aso = asr + 32 * 132;        // [32][132]  x rows (skip source)

    int tid = threadIdx.x, lane = tid & 31, wp = tid >> 5;
    int c0 = lane * 4, r0 = wp * 4;

    for (int i = tid; i < 128 * 128; i += 256) {
        int c = i >> 7, k = i & 127;
        wtr[k * 132 + c] = Wrel[i];
        wto[k * 132 + c] = Wroot[i];
    }
    float4 bv = *(const float4*)&brel[c0];
    float4 gv = *(const float4*)&gamma[c0];
    float4 bt = *(const float4*)&beta[c0];
    __syncthreads();

    int nch = (n + 31) >> 5;
    for (int ch = blockIdx.x; ch < nch; ch += gridDim.x) {
        int row0 = ch << 5;
        for (int i = tid; i < 32 * 128; i += 256) {
            int r = i >> 7, k = i & 127, gr = row0 + r;
            float av = 0.f, xv = 0.f;
            if (gr < n) { av = g_aggf[gr * 128 + k]; xv = x[gr * 128 + k]; }
            asr[r * 132 + k] = av;
            aso[r * 132 + k] = xv;
        }
        __syncthreads();

        float4 acc[4];
        #pragma unroll
        for (int j = 0; j < 4; j++) acc[j] = make_float4(0.f, 0.f, 0.f, 0.f);

        #pragma unroll 2
        for (int k = 0; k < 128; k += 4) {
            float4 wr0 = *(const float4*)&wtr[(k + 0) * 132 + c0];
            float4 wr1 = *(const float4*)&wtr[(k + 1) * 132 + c0];
            float4 wr2 = *(const float4*)&wtr[(k + 2) * 132 + c0];
            float4 wr3 = *(const float4*)&wtr[(k + 3) * 132 + c0];
            float4 wo0 = *(const float4*)&wto[(k + 0) * 132 + c0];
            float4 wo1 = *(const float4*)&wto[(k + 1) * 132 + c0];
            float4 wo2 = *(const float4*)&wto[(k + 2) * 132 + c0];
            float4 wo3 = *(const float4*)&wto[(k + 3) * 132 + c0];
            #pragma unroll
            for (int j = 0; j < 4; j++) {
                float4 a1 = *(const float4*)&asr[(r0 + j) * 132 + k];
                float4 a2 = *(const float4*)&aso[(r0 + j) * 132 + k];
                fma4(acc[j], a1.x, wr0); fma4(acc[j], a2.x, wo0);
                fma4(acc[j], a1.y, wr1); fma4(acc[j], a2.y, wo1);
                fma4(acc[j], a1.z, wr2); fma4(acc[j], a2.z, wo2);
                fma4(acc[j], a1.w, wr3); fma4(acc[j], a2.w, wo3);
            }
        }

        #pragma unroll
        for (int j = 0; j < 4; j++) {
            int r = row0 + r0 + j;
            float4 sk = *(const float4*)&aso[(r0 + j) * 132 + c0];
            float4 h;
            h.x = gelu_exact(acc[j].x + bv.x) + sk.x;
            h.y = gelu_exact(acc[j].y + bv.y) + sk.y;
            h.z = gelu_exact(acc[j].z + bv.z) + sk.z;
            h.w = gelu_exact(acc[j].w + bv.w) + sk.w;
            float s = h.x + h.y + h.z + h.w;
            float q = h.x * h.x + h.y * h.y + h.z * h.z + h.w * h.w;
            #pragma unroll
            for (int o = 16; o; o >>= 1) {
                s += __shfl_xor_sync(0xffffffffu, s, o);
                q += __shfl_xor_sync(0xffffffffu, q, o);
            }
            float mu = s * (1.f / D);
            float var = fmaxf(q * (1.f / D) - mu * mu, 0.f);
            float rs = rsqrtf(var + LN_EPS);
            float4 y;
            y.x = (h.x - mu) * rs * gv.x + bt.x;
            y.y = (h.y - mu) * rs * gv.y + bt.y;
            y.z = (h.z - mu) * rs * gv.z + bt.z;
            y.w = (h.w - mu) * rs * gv.w + bt.w;
            if (r < n) *(float4*)&g_h[r * 128 + c0] = y;
        }
        __syncthreads();
    }
}

// ---------------- K4: out = LN( gelu(h@linW^T + lb) + h ) ----------------
__global__ void __launch_bounds__(256, 2)
k_gemm2(const float* __restrict__ lw, const float* __restrict__ lb,
        const float* __restrict__ gamma, const float* __restrict__ beta,
        float* __restrict__ out, int n) {
    extern __shared__ float sm[];
    float* wt = sm;                 // [128][132]
    float* as = wt + 128 * 132;     // [32][132] h rows (also skip source)

    int tid = threadIdx.x, lane = tid & 31, wp = tid >> 5;
    int c0 = lane * 4, r0 = wp * 4;

    for (int i = tid; i < 128 * 128; i += 256) {
        int c = i >> 7, k = i & 127;
        wt[k * 132 + c] = lw[i];
    }
    float4 bv = *(const float4*)&lb[c0];
    float4 gv = *(const float4*)&gamma[c0];
    float4 bt = *(const float4*)&beta[c0];
    __syncthreads();

    int nch = (n + 31) >> 5;
    for (int ch = blockIdx.x; ch < nch; ch += gridDim.x) {
        int row0 = ch << 5;
        for (int i = tid; i < 32 * 128; i += 256) {
            int r = i >> 7, k = i & 127, gr = row0 + r;
            as[r * 132 + k] = (gr < n) ? g_h[gr * 128 + k] : 0.f;
        }
        __syncthreads();

        float4 acc[4];
        #pragma unroll
        for (int j = 0; j < 4; j++) acc[j] = make_float4(0.f, 0.f, 0.f, 0.f);

        #pragma unroll 2
        for (int k = 0; k < 128; k += 4) {
            float4 w0 = *(const float4*)&wt[(k + 0) * 132 + c0];
            float4 w1 = *(const float4*)&wt[(k + 1) * 132 + c0];
            float4 w2 = *(const float4*)&wt[(k + 2) * 132 + c0];
            float4 w3 = *(const float4*)&wt[(k + 3) * 132 + c0];
            #pragma unroll
            for (int j = 0; j < 4; j++) {
                float4 a1 = *(const float4*)&as[(r0 + j) * 132 + k];
                fma4(acc[j], a1.x, w0);
                fma4(acc[j], a1.y, w1);
                fma4(acc[j], a1.z, w2);
                fma4(acc[j], a1.w, w3);
            }
        }

        #pragma unroll
        for (int j = 0; j < 4; j++) {
            int r = row0 + r0 + j;
            float4 sk = *(const float4*)&as[(r0 + j) * 132 + c0];
            float4 h;
            h.x = gelu_exact(acc[j].x + bv.x) + sk.x;
            h.y = gelu_exact(acc[j].y + bv.y) + sk.y;
            h.z = gelu_exact(acc[j].z + bv.z) + sk.z;
            h.w = gelu_exact(acc[j].w + bv.w) + sk.w;
            float s = h.x + h.y + h.z + h.w;
            float q = h.x * h.x + h.y * h.y + h.z * h.z + h.w * h.w;
            #pragma unroll
            for (int o = 16; o; o >>= 1) {
                s += __shfl_xor_sync(0xffffffffu, s, o);
                q += __shfl_xor_sync(0xffffffffu, q, o);
            }
            float mu = s * (1.f / D);
            float var = fmaxf(q * (1.f / D) - mu * mu, 0.f);
            float rs = rsqrtf(var + LN_EPS);
            float4 y;
            y.x = (h.x - mu) * rs * gv.x + bt.x;
            y.y = (h.y - mu) * rs * gv.y + bt.y;
            y.z = (h.z - mu) * rs * gv.z + bt.z;
            y.w = (h.w - mu) * rs * gv.w + bt.w;
            if (r < n) *(float4*)&out[r * 128 + c0] = y;
        }
        __syncthreads();
    }
}

// ---------------- launch ----------------
extern "C" void kernel_launch(void* const* d_in, const int* in_sizes, int n_in,
                              void* d_out, int out_size) {
    const float* x     = (const float*)d_in[0];
    const int*   ei    = (const int*)d_in[1];
    const float* ew    = (const float*)d_in[2];
    const float* Wrel  = (const float*)d_in[3];
    const float* brel  = (const float*)d_in[4];
    const float* Wroot = (const float*)d_in[5];
    const float* linW  = (const float*)d_in[6];
    const float* linb  = (const float*)d_in[7];
    const float* gamma = (const float*)d_in[8];
    const float* beta  = (const float*)d_in[9];
    float* out = (float*)d_out;

    int n = in_sizes[0] / D;
    int e = in_sizes[2];

    size_t smem1 = (size_t)(2 * 128 * 132 + 2 * 32 * 132) * 4;  // 168,960 B
    size_t smem2 = (size_t)(128 * 132 + 32 * 132) * 4;          //  84,480 B
    cudaFuncSetAttribute(k_gemm1, cudaFuncAttributeMaxDynamicSharedMemorySize, (int)smem1);
    cudaFuncSetAttribute(k_gemm2, cudaFuncAttributeMaxDynamicSharedMemorySize, (int)smem2);

    k_detect<<<1, 256>>>(ei);
    k_zero<<<(n + 255) / 256, 256>>>(n);
    k_count<<<(e + 255) / 256, 256>>>(ei, e);
    k_scan<<<1, 1024>>>(n);
    k_place<<<(e + 255) / 256, 256>>>(ei, ew, e);
    k_agg<<<(n + 7) / 8, 256>>>(x, n);
    k_gemm1<<<148, 256, smem1>>>(x, Wrel, brel, Wroot, gamma, beta, n);
    k_gemm2<<<296, 256, smem2>>>(linW, linb, gamma, beta, out, n);
    if (out_size >= n * D + e)
        cudaMemcpyAsync(out + (size_t)n * D, ew, (size_t)e * sizeof(float),
                        cudaMemcpyDeviceToDevice);
}